// round 2
// baseline (speedup 1.0000x reference)
#include <cuda_runtime.h>
#include <math.h>

#define NE    8
#define NB    100000
#define DIM   1024
#define NSUP  128
#define KSEL  15000u

// ---------------- scratch ----------------
__device__ float    g_q[NE][DIM];
__device__ float    g_sim[NE * NB];
__device__ float    g_invnorm[NB];
__device__ unsigned g_h1[NE][256];       // level-1 8-bit histogram (filled by kB)
__device__ unsigned g_thr_key[NE];
__device__ int      g_tiecut[NE];
__device__ float    g_approx[NE][DIM];

__device__ __forceinline__ unsigned tokey(float f) {
    unsigned b = __float_as_uint(f);
    return b ^ ((unsigned)((int)b >> 31) | 0x80000000u);
}
__device__ __forceinline__ void fma2(unsigned long long& d, unsigned long long a, unsigned long long b) {
    asm("fma.rn.f32x2 %0, %1, %2, %0;" : "+l"(d) : "l"(a), "l"(b));
}
__device__ __forceinline__ float sumpair(unsigned long long a) {
    float lo, hi;
    asm("mov.b64 {%0,%1}, %2;" : "=f"(lo), "=f"(hi) : "l"(a));
    return lo + hi;
}

// ---------------- init: zero h1 + approx (tiny) ----------------
__global__ void kInit() {
    unsigned i = blockIdx.x * blockDim.x + threadIdx.x;
    unsigned stride = gridDim.x * blockDim.x;
    unsigned* h1 = &g_h1[0][0];
    for (unsigned k = i; k < NE * 256u; k += stride) h1[k] = 0u;
    float* ap = &g_approx[0][0];
    for (unsigned k = i; k < NE * DIM; k += stride) ap[k] = 0.0f;
}

// ---------------- A: per-episode support mean of normalized rows ----------------
__global__ void __launch_bounds__(1024) kA(const float* __restrict__ feats) {
    int e = blockIdx.x;
    int tid = threadIdx.x, lane = tid & 31, wid = tid >> 5;
    __shared__ float s_inv[NSUP];
    const float* fe = feats + (size_t)e * DIM * DIM;
    #pragma unroll
    for (int rr = 0; rr < NSUP / 32; rr++) {
        int r = wid + rr * 32;
        const float4* row4 = (const float4*)(fe + (size_t)r * DIM);
        float s = 0.f;
        #pragma unroll
        for (int k = 0; k < 8; k++) {
            float4 v = row4[k * 32 + lane];
            s += v.x * v.x + v.y * v.y + v.z * v.z + v.w * v.w;
        }
        #pragma unroll
        for (int o = 16; o > 0; o >>= 1) s += __shfl_xor_sync(0xFFFFFFFFu, s, o);
        if (lane == 0) s_inv[r] = rsqrtf(fmaxf(s, 1e-24f));
    }
    __syncthreads();
    float acc = 0.f;
    #pragma unroll 8
    for (int r = 0; r < NSUP; r++) acc += fe[(size_t)r * DIM + tid] * s_inv[r];
    g_q[e][tid] = acc;
}

// ---------------- B: sims via packed f32x2; fused 8-bit level-1 histogram ------
__global__ void __launch_bounds__(128) kB(const float* __restrict__ base) {
    __shared__ ulonglong2 sq[NE * 256];       // 32 KB: q as pairs
    __shared__ unsigned bh[NE * 256];         // 8 KB: private level-1 hist
    for (int i = threadIdx.x; i < NE * 256; i += 128) sq[i] = ((const ulonglong2*)g_q)[i];
    for (int i = threadIdx.x; i < NE * 256; i += 128) bh[i] = 0u;
    __syncthreads();
    int lane = threadIdx.x & 31;
    int gw = (blockIdx.x * 128 + threadIdx.x) >> 5;
    int nw = (gridDim.x * 128) >> 5;
    for (int g = gw; g < NB / 4; g += nw) {
        const ulonglong2* p0 = (const ulonglong2*)(base + (size_t)(4 * g) * DIM);
        const ulonglong2* p1 = p0 + 256;
        const ulonglong2* p2 = p0 + 512;
        const ulonglong2* p3 = p0 + 768;
        unsigned long long acc[4][8];
        unsigned long long ss[4];
        #pragma unroll
        for (int r = 0; r < 4; r++) {
            ss[r] = 0ull;
            #pragma unroll
            for (int e = 0; e < 8; e++) acc[r][e] = 0ull;
        }
        #pragma unroll 2
        for (int k = 0; k < 8; k++) {
            ulonglong2 v0 = p0[k * 32 + lane];
            ulonglong2 v1 = p1[k * 32 + lane];
            ulonglong2 v2 = p2[k * 32 + lane];
            ulonglong2 v3 = p3[k * 32 + lane];
            fma2(ss[0], v0.x, v0.x); fma2(ss[0], v0.y, v0.y);
            fma2(ss[1], v1.x, v1.x); fma2(ss[1], v1.y, v1.y);
            fma2(ss[2], v2.x, v2.x); fma2(ss[2], v2.y, v2.y);
            fma2(ss[3], v3.x, v3.x); fma2(ss[3], v3.y, v3.y);
            #pragma unroll
            for (int e = 0; e < 8; e++) {
                ulonglong2 q = sq[e * 256 + k * 32 + lane];
                fma2(acc[0][e], v0.x, q.x); fma2(acc[0][e], v0.y, q.y);
                fma2(acc[1][e], v1.x, q.x); fma2(acc[1][e], v1.y, q.y);
                fma2(acc[2][e], v2.x, q.x); fma2(acc[2][e], v2.y, q.y);
                fma2(acc[3][e], v3.x, q.x); fma2(acc[3][e], v3.y, q.y);
            }
        }
        #pragma unroll
        for (int r = 0; r < 4; r++) {
            float s = sumpair(ss[r]);
            #pragma unroll
            for (int o = 16; o > 0; o >>= 1) s += __shfl_xor_sync(0xFFFFFFFFu, s, o);
            float inv = rsqrtf(fmaxf(s, 1e-24f));
            if (lane == 0) g_invnorm[4 * g + r] = inv;
            #pragma unroll
            for (int e = 0; e < 8; e++) {
                float d = sumpair(acc[r][e]);
                #pragma unroll
                for (int o = 16; o > 0; o >>= 1) d += __shfl_xor_sync(0xFFFFFFFFu, d, o);
                if (lane == 0) {
                    float sim = d * inv;
                    g_sim[e * NB + 4 * g + r] = sim;
                    atomicAdd(&bh[e * 256 + (tokey(sim) >> 24)], 1u);
                }
            }
        }
    }
    __syncthreads();
    for (int i = threadIdx.x; i < NE * 256; i += 128) {
        unsigned c = bh[i];
        if (c) atomicAdd(&(&g_h1[0][0])[i], c);
    }
}

// ---------------- C: exact K-th key; one block per episode ----------------
// block-wide descending find over a 256-bin shared histogram
__device__ __forceinline__ void find256(unsigned* h, unsigned* sfx, unsigned target,
                                        unsigned* obin, unsigned* orank) {
    int t = threadIdx.x;
    if (t < 256) sfx[t] = h[t];
    __syncthreads();
    #pragma unroll
    for (int o = 1; o < 256; o <<= 1) {
        unsigned v = 0;
        if (t < 256 && t + o < 256) v = sfx[t + o];
        __syncthreads();
        if (t < 256) sfx[t] += v;
        __syncthreads();
    }
    if (t < 256) {
        unsigned tot = sfx[t], above = tot - h[t];    // above = count in bins > t
        if (above < target && target <= tot) { *obin = (unsigned)t; *orank = target - above; }
    }
    __syncthreads();
}

__global__ void __launch_bounds__(1024) kSel() {
    int e = blockIdx.x;
    const float* sims = g_sim + (size_t)e * NB;
    int t = threadIdx.x;
    __shared__ unsigned h[256], sfx[256];
    __shared__ unsigned hrep[8][256];
    __shared__ unsigned s_bin, s_rank;
    __shared__ int s_idx[4096];
    __shared__ int s_cnt;

    if (t < 256) h[t] = g_h1[e][t];
    __syncthreads();
    find256(h, sfx, KSEL, &s_bin, &s_rank);
    unsigned prefix = s_bin;
    unsigned rank = s_rank;
    __syncthreads();

    int rep = (t >> 5) & 7;
    #pragma unroll 1
    for (int lvl = 0; lvl < 3; lvl++) {
        int shift_chk = 24 - lvl * 8;
        int shift_bin = shift_chk - 8;
        for (int i = t; i < 8 * 256; i += 1024) ((unsigned*)hrep)[i] = 0u;
        if (lvl == 2 && t == 0) s_cnt = 0;
        __syncthreads();
        for (int i = t; i < NB; i += 1024) {
            unsigned key = tokey(sims[i]);
            if ((key >> shift_chk) == prefix) {
                atomicAdd(&hrep[rep][(key >> shift_bin) & 0xFFu], 1u);
                if (lvl == 2) { int p = atomicAdd(&s_cnt, 1); if (p < 4096) s_idx[p] = i; }
            }
        }
        __syncthreads();
        if (t < 256) {
            unsigned s = 0;
            #pragma unroll
            for (int r2 = 0; r2 < 8; r2++) s += hrep[r2][t];
            h[t] = s;
        }
        __syncthreads();
        find256(h, sfx, rank, &s_bin, &s_rank);
        prefix = (prefix << 8) | s_bin;
        rank = s_rank;
        __syncthreads();
    }
    unsigned thr = prefix;
    if (t == 0) g_thr_key[e] = thr;
    __syncthreads();

    // fallback: if the 24-bit-prefix candidate list overflowed, rebuild with exact-key filter
    if (s_cnt > 4096) {
        __syncthreads();
        if (t == 0) s_cnt = 0;
        __syncthreads();
        for (int i = t; i < NB; i += 1024) {
            if (tokey(sims[i]) == thr) { int p = atomicAdd(&s_cnt, 1); if (p < 4096) s_idx[p] = i; }
        }
        __syncthreads();
    }
    int cnt = min(s_cnt, 4096);
    // tie-break by lowest index (jax.lax.top_k): cut = rank-th smallest tie index
    for (int i = t; i < cnt; i += 1024) {
        int my = s_idx[i];
        if (tokey(sims[my]) == thr) {
            int below = 0;
            for (int j = 0; j < cnt; j++) {
                int oj = s_idx[j];
                if (oj < my && tokey(sims[oj]) == thr) below++;
            }
            if (below == (int)rank - 1) g_tiecut[e] = my;
        }
    }
}

// ---------------- D: weighted accumulation (f32x2) ----------------
__global__ void __launch_bounds__(256) kD(const float* __restrict__ base) {
    __shared__ unsigned long long s_w[32][8];   // per-row weight, duplicated in both halves
    int tid = threadIdx.x;
    int we = tid >> 5, wr = tid & 31;
    unsigned long long accA[8], accB[8];
    #pragma unroll
    for (int e = 0; e < 8; e++) { accA[e] = 0ull; accB[e] = 0ull; }
    unsigned thr = g_thr_key[we];
    int cut = g_tiecut[we];
    const ulonglong2* b2 = (const ulonglong2*)base;
    for (int tile = blockIdx.x; tile < NB / 32; tile += gridDim.x) {
        int row0 = tile * 32;
        {
            int row = row0 + wr;
            float sim = g_sim[we * NB + row];
            unsigned key = tokey(sim);
            bool sel = (key > thr) || (key == thr && row <= cut);
            float w = sel ? (sqrtf(fmaxf(sim, 0.f)) * g_invnorm[row]) : 0.f;
            unsigned u = __float_as_uint(w);
            s_w[wr][we] = ((unsigned long long)u << 32) | u;
        }
        __syncthreads();
        #pragma unroll 2
        for (int r = 0; r < 32; r++) {
            ulonglong2 w01 = *(const ulonglong2*)&s_w[r][0];
            ulonglong2 w23 = *(const ulonglong2*)&s_w[r][2];
            ulonglong2 w45 = *(const ulonglong2*)&s_w[r][4];
            ulonglong2 w67 = *(const ulonglong2*)&s_w[r][6];
            unsigned long long any = w01.x | w01.y | w23.x | w23.y | w45.x | w45.y | w67.x | w67.y;
            if (any) {                                  // warp-uniform
                ulonglong2 v = b2[(size_t)(row0 + r) * 256 + tid];
                fma2(accA[0], w01.x, v.x); fma2(accB[0], w01.x, v.y);
                fma2(accA[1], w01.y, v.x); fma2(accB[1], w01.y, v.y);
                fma2(accA[2], w23.x, v.x); fma2(accB[2], w23.x, v.y);
                fma2(accA[3], w23.y, v.x); fma2(accB[3], w23.y, v.y);
                fma2(accA[4], w45.x, v.x); fma2(accB[4], w45.x, v.y);
                fma2(accA[5], w45.y, v.x); fma2(accB[5], w45.y, v.y);
                fma2(accA[6], w67.x, v.x); fma2(accB[6], w67.x, v.y);
                fma2(accA[7], w67.y, v.x); fma2(accB[7], w67.y, v.y);
            }
        }
        __syncthreads();
    }
    #pragma unroll
    for (int e = 0; e < 8; e++) {
        float ax, ay, az, aw;
        asm("mov.b64 {%0,%1}, %2;" : "=f"(ax), "=f"(ay) : "l"(accA[e]));
        asm("mov.b64 {%0,%1}, %2;" : "=f"(az), "=f"(aw) : "l"(accB[e]));
        atomicAdd(&g_approx[e][4 * tid + 0], ax);
        atomicAdd(&g_approx[e][4 * tid + 1], ay);
        atomicAdd(&g_approx[e][4 * tid + 2], az);
        atomicAdd(&g_approx[e][4 * tid + 3], aw);
    }
}

// ---------------- E: normalize approx ----------------
__global__ void __launch_bounds__(256) kE() {
    int e = blockIdx.x, tid = threadIdx.x;
    float4* a4 = (float4*)g_approx[e];
    float4 v = a4[tid];
    float ss = v.x * v.x + v.y * v.y + v.z * v.z + v.w * v.w;
    int lane = tid & 31, wid = tid >> 5;
    #pragma unroll
    for (int o = 16; o > 0; o >>= 1) ss += __shfl_xor_sync(0xFFFFFFFFu, ss, o);
    __shared__ float s_s[8];
    __shared__ float s_inv;
    if (lane == 0) s_s[wid] = ss;
    __syncthreads();
    if (tid == 0) {
        float t = 0.f;
        for (int i = 0; i < 8; i++) t += s_s[i];
        s_inv = rsqrtf(fmaxf(t, 1e-24f));
    }
    __syncthreads();
    float inv = s_inv;
    v.x *= inv; v.y *= inv; v.z *= inv; v.w *= inv;
    a4[tid] = v;
}

// ---------------- F: orthogonalize every feature row ----------------
__global__ void __launch_bounds__(256) kF(const float* __restrict__ feats, float* __restrict__ out) {
    int b = blockIdx.x;
    int e = b >> 7;
    int lane = threadIdx.x & 31, warp = threadIdx.x >> 5;
    int rowInEp = (b & 127) * 8 + warp;
    size_t off = ((size_t)e * DIM + rowInEp) * DIM;
    const float4* f4 = (const float4*)(feats + off);
    float4* o4 = (float4*)(out + off);
    const float4* a4 = (const float4*)g_approx[e];
    float4 v[8], a[8];
    float ss = 0.f, dd = 0.f;
    #pragma unroll
    for (int k = 0; k < 8; k++) {
        v[k] = f4[k * 32 + lane];
        a[k] = a4[k * 32 + lane];
        ss += v[k].x * v[k].x + v[k].y * v[k].y + v[k].z * v[k].z + v[k].w * v[k].w;
        dd += v[k].x * a[k].x + v[k].y * a[k].y + v[k].z * a[k].z + v[k].w * a[k].w;
    }
    #pragma unroll
    for (int o = 16; o > 0; o >>= 1) {
        ss += __shfl_xor_sync(0xFFFFFFFFu, ss, o);
        dd += __shfl_xor_sync(0xFFFFFFFFu, dd, o);
    }
    float invf = rsqrtf(fmaxf(ss, 1e-24f));
    float c = dd * invf;
    float sc = rsqrtf(fmaxf(1.0f - c * c, 1e-24f));
    #pragma unroll
    for (int k = 0; k < 8; k++) {
        float4 r;
        r.x = (v[k].x * invf - c * a[k].x) * sc;
        r.y = (v[k].y * invf - c * a[k].y) * sc;
        r.z = (v[k].z * invf - c * a[k].z) * sc;
        r.w = (v[k].w * invf - c * a[k].w) * sc;
        o4[k * 32 + lane] = r;
    }
}

// ---------------- launch ----------------
extern "C" void kernel_launch(void* const* d_in, const int* in_sizes, int n_in,
                              void* d_out, int out_size) {
    const float* feats = (const float*)d_in[0];
    const float* base  = (const float*)d_in[1];
    float* out = (float*)d_out;
    (void)in_sizes; (void)n_in; (void)out_size;

    kInit<<<10, 1024>>>();
    kA<<<NE, 1024>>>(feats);
    kB<<<1480, 128>>>(base);
    kSel<<<NE, 1024>>>();
    kD<<<592, 256>>>(base);
    kE<<<NE, 256>>>();
    kF<<<1024, 256>>>(feats, out);
}

// round 3
// speedup vs baseline: 1.0631x; 1.0631x over previous
#include <cuda_runtime.h>
#include <math.h>

#define NE    8
#define NB    100000
#define DIM   1024
#define NSUP  128
#define KSEL  15000u
#define MAXC  4096

// ---------------- scratch ----------------
__device__ float    g_q[NE][DIM];
__device__ float    g_sim[NE * NB];
__device__ float    g_invnorm[NB];
__device__ unsigned g_h1[NE][256];        // level-1 8-bit histogram (filled by kB)
__device__ unsigned g_h2[NE][65536];      // level-2 16-bit histogram (mantissa bits 23..8)
__device__ unsigned g_prefix24[NE];
__device__ unsigned g_rank2[NE];
__device__ int      g_cand[NE][MAXC];
__device__ int      g_ccnt[NE];
__device__ unsigned g_thr_key[NE];
__device__ int      g_tiecut[NE];
__device__ float    g_approx[NE][DIM];

__device__ __forceinline__ unsigned tokey(float f) {
    unsigned b = __float_as_uint(f);
    return b ^ ((unsigned)((int)b >> 31) | 0x80000000u);
}
__device__ __forceinline__ void fma2(unsigned long long& d, unsigned long long a, unsigned long long b) {
    asm("fma.rn.f32x2 %0, %1, %2, %0;" : "+l"(d) : "l"(a), "l"(b));
}
__device__ __forceinline__ float sumpair(unsigned long long a) {
    float lo, hi;
    asm("mov.b64 {%0,%1}, %2;" : "=f"(lo), "=f"(hi) : "l"(a));
    return lo + hi;
}

// ---------------- init: zero h1, h2, approx, counters ----------------
__global__ void kInit() {
    unsigned i = blockIdx.x * blockDim.x + threadIdx.x;
    unsigned stride = gridDim.x * blockDim.x;
    unsigned* h2 = &g_h2[0][0];
    for (unsigned k = i; k < NE * 65536u; k += stride) h2[k] = 0u;
    unsigned* h1 = &g_h1[0][0];
    for (unsigned k = i; k < NE * 256u; k += stride) h1[k] = 0u;
    float* ap = &g_approx[0][0];
    for (unsigned k = i; k < NE * DIM; k += stride) ap[k] = 0.0f;
    if (i < NE) g_ccnt[i] = 0;
}

// ---------------- A: per-episode support mean of normalized rows ----------------
__global__ void __launch_bounds__(1024) kA(const float* __restrict__ feats) {
    int e = blockIdx.x;
    int tid = threadIdx.x, lane = tid & 31, wid = tid >> 5;
    __shared__ float s_inv[NSUP];
    const float* fe = feats + (size_t)e * DIM * DIM;
    #pragma unroll
    for (int rr = 0; rr < NSUP / 32; rr++) {
        int r = wid + rr * 32;
        const float4* row4 = (const float4*)(fe + (size_t)r * DIM);
        float s = 0.f;
        #pragma unroll
        for (int k = 0; k < 8; k++) {
            float4 v = row4[k * 32 + lane];
            s += v.x * v.x + v.y * v.y + v.z * v.z + v.w * v.w;
        }
        #pragma unroll
        for (int o = 16; o > 0; o >>= 1) s += __shfl_xor_sync(0xFFFFFFFFu, s, o);
        if (lane == 0) s_inv[r] = rsqrtf(fmaxf(s, 1e-24f));
    }
    __syncthreads();
    float acc = 0.f;
    #pragma unroll 8
    for (int r = 0; r < NSUP; r++) acc += fe[(size_t)r * DIM + tid] * s_inv[r];
    g_q[e][tid] = acc;
}

// ---------------- B: sims via packed f32x2; fused 8-bit level-1 histogram ------
__global__ void __launch_bounds__(128) kB(const float* __restrict__ base) {
    __shared__ ulonglong2 sq[NE * 256];       // 32 KB
    __shared__ unsigned bh[NE * 256];         // 8 KB private level-1 hist
    for (int i = threadIdx.x; i < NE * 256; i += 128) sq[i] = ((const ulonglong2*)g_q)[i];
    for (int i = threadIdx.x; i < NE * 256; i += 128) bh[i] = 0u;
    __syncthreads();
    int lane = threadIdx.x & 31;
    int gw = (blockIdx.x * 128 + threadIdx.x) >> 5;
    int nw = (gridDim.x * 128) >> 5;
    for (int g = gw; g < NB / 4; g += nw) {
        const ulonglong2* p0 = (const ulonglong2*)(base + (size_t)(4 * g) * DIM);
        const ulonglong2* p1 = p0 + 256;
        const ulonglong2* p2 = p0 + 512;
        const ulonglong2* p3 = p0 + 768;
        unsigned long long acc[4][8];
        unsigned long long ss[4];
        #pragma unroll
        for (int r = 0; r < 4; r++) {
            ss[r] = 0ull;
            #pragma unroll
            for (int e = 0; e < 8; e++) acc[r][e] = 0ull;
        }
        #pragma unroll 2
        for (int k = 0; k < 8; k++) {
            ulonglong2 v0 = p0[k * 32 + lane];
            ulonglong2 v1 = p1[k * 32 + lane];
            ulonglong2 v2 = p2[k * 32 + lane];
            ulonglong2 v3 = p3[k * 32 + lane];
            fma2(ss[0], v0.x, v0.x); fma2(ss[0], v0.y, v0.y);
            fma2(ss[1], v1.x, v1.x); fma2(ss[1], v1.y, v1.y);
            fma2(ss[2], v2.x, v2.x); fma2(ss[2], v2.y, v2.y);
            fma2(ss[3], v3.x, v3.x); fma2(ss[3], v3.y, v3.y);
            #pragma unroll
            for (int e = 0; e < 8; e++) {
                ulonglong2 q = sq[e * 256 + k * 32 + lane];
                fma2(acc[0][e], v0.x, q.x); fma2(acc[0][e], v0.y, q.y);
                fma2(acc[1][e], v1.x, q.x); fma2(acc[1][e], v1.y, q.y);
                fma2(acc[2][e], v2.x, q.x); fma2(acc[2][e], v2.y, q.y);
                fma2(acc[3][e], v3.x, q.x); fma2(acc[3][e], v3.y, q.y);
            }
        }
        #pragma unroll
        for (int r = 0; r < 4; r++) {
            float s = sumpair(ss[r]);
            #pragma unroll
            for (int o = 16; o > 0; o >>= 1) s += __shfl_xor_sync(0xFFFFFFFFu, s, o);
            float inv = rsqrtf(fmaxf(s, 1e-24f));
            if (lane == 0) g_invnorm[4 * g + r] = inv;
            #pragma unroll
            for (int e = 0; e < 8; e++) {
                float d = sumpair(acc[r][e]);
                #pragma unroll
                for (int o = 16; o > 0; o >>= 1) d += __shfl_xor_sync(0xFFFFFFFFu, d, o);
                if (lane == 0) {
                    float sim = d * inv;
                    g_sim[e * NB + 4 * g + r] = sim;
                    atomicAdd(&bh[e * 256 + (tokey(sim) >> 24)], 1u);
                }
            }
        }
    }
    __syncthreads();
    for (int i = threadIdx.x; i < NE * 256; i += 128) {
        unsigned c = bh[i];
        if (c) atomicAdd(&(&g_h1[0][0])[i], c);
    }
}

// ---------------- selection helpers ----------------
// descending find over a 256-bin shared histogram (callers: >=256 threads)
__device__ __forceinline__ void find256(unsigned* h, unsigned* sfx, unsigned target,
                                        unsigned* obin, unsigned* orank) {
    int t = threadIdx.x;
    if (t < 256) sfx[t] = h[t];
    __syncthreads();
    #pragma unroll
    for (int o = 1; o < 256; o <<= 1) {
        unsigned v = 0;
        if (t < 256 && t + o < 256) v = sfx[t + o];
        __syncthreads();
        if (t < 256) sfx[t] += v;
        __syncthreads();
    }
    if (t < 256) {
        unsigned tot = sfx[t], above = tot - h[t];
        if (above < target && target <= tot) { *obin = (unsigned)t; if (orank) *orank = target - above; }
    }
    __syncthreads();
}

// descending find over 65536-bin global histogram (1024-thread block)
__device__ __forceinline__ void find64k(const unsigned* __restrict__ hist, unsigned target,
                                        unsigned* obin, unsigned* orank) {
    int t = threadIdx.x, lane = t & 31, wid = t >> 5;
    unsigned base = (unsigned)t * 64u;
    unsigned part = 0;
    #pragma unroll 8
    for (int j = 0; j < 64; j++) part += hist[base + j];
    unsigned x = part;
    #pragma unroll
    for (int o = 1; o < 32; o <<= 1) { unsigned y = __shfl_up_sync(0xFFFFFFFFu, x, o); if (lane >= o) x += y; }
    __shared__ unsigned s_ws[32];
    __shared__ unsigned s_total;
    if (lane == 31) s_ws[wid] = x;
    __syncthreads();
    if (wid == 0) {
        unsigned w = s_ws[lane];
        #pragma unroll
        for (int o = 1; o < 32; o <<= 1) { unsigned y = __shfl_up_sync(0xFFFFFFFFu, w, o); if (lane >= o) w += y; }
        s_ws[lane] = w;
        if (lane == 31) s_total = w;
    }
    __syncthreads();
    unsigned incl = x + (wid ? s_ws[wid - 1] : 0u);
    unsigned above = s_total - incl;
    if (above < target && target <= above + part) {
        unsigned cum = above;
        for (int j = 63; j >= 0; j--) {
            unsigned c = hist[base + j];
            if (cum + c >= target) { *obin = base + j; *orank = target - cum; break; }
            cum += c;
        }
    }
    __syncthreads();
}

// ---------------- Hist2: grid-wide filtered 16-bit histogram ----------------
__global__ void __launch_bounds__(1024) kHist2() {
    int e = blockIdx.y;
    int t = threadIdx.x;
    __shared__ unsigned h[256], sfx[256];
    __shared__ unsigned s_bin1;
    if (t < 256) h[t] = g_h1[e][t];
    __syncthreads();
    find256(h, sfx, KSEL, &s_bin1, 0);
    unsigned b1 = s_bin1;
    const float* sims = g_sim + (size_t)e * NB;
    int i0 = blockIdx.x * 2048 + t;
    #pragma unroll
    for (int rr = 0; rr < 2; rr++) {
        int i = i0 + rr * 1024;
        if (i < NB) {
            unsigned key = tokey(sims[i]);
            if ((key >> 24) == b1) atomicAdd(&g_h2[e][(key >> 8) & 0xFFFFu], 1u);
        }
    }
}

// ---------------- Find2: exact 24-bit prefix + rank ----------------
__global__ void __launch_bounds__(1024) kFind2() {
    int e = blockIdx.x;
    int t = threadIdx.x;
    __shared__ unsigned h[256], sfx[256];
    __shared__ unsigned s_bin1, s_rank1, s_bin2, s_rank2;
    if (t < 256) h[t] = g_h1[e][t];
    __syncthreads();
    find256(h, sfx, KSEL, &s_bin1, &s_rank1);
    find64k(g_h2[e], s_rank1, &s_bin2, &s_rank2);
    if (t == 0) {
        g_prefix24[e] = (s_bin1 << 16) | s_bin2;
        g_rank2[e] = s_rank2;
    }
}

// ---------------- Cand: grid-wide collect of 24-bit-prefix matches ----------------
__global__ void __launch_bounds__(1024) kCand() {
    int e = blockIdx.y;
    unsigned pfx = g_prefix24[e];
    const float* sims = g_sim + (size_t)e * NB;
    int i0 = blockIdx.x * 2048 + threadIdx.x;
    #pragma unroll
    for (int rr = 0; rr < 2; rr++) {
        int i = i0 + rr * 1024;
        if (i < NB) {
            unsigned key = tokey(sims[i]);
            if ((key >> 8) == pfx) {
                int p = atomicAdd(&g_ccnt[e], 1);
                if (p < MAXC) g_cand[e][p] = i;
            }
        }
    }
}

// ---------------- Resolve: exact 32-bit threshold + lowest-index tie cut ----------
__global__ void __launch_bounds__(256) kResolve() {
    int e = blockIdx.x;
    int cnt = min(g_ccnt[e], MAXC);
    unsigned rank = g_rank2[e];
    __shared__ int sidx[MAXC];
    __shared__ unsigned skey[MAXC];
    const float* sims = g_sim + (size_t)e * NB;
    for (int i = threadIdx.x; i < cnt; i += 256) {
        int idx = g_cand[e][i];
        sidx[i] = idx;
        skey[i] = tokey(sims[idx]);
    }
    __syncthreads();
    for (int i = threadIdx.x; i < cnt; i += 256) {
        int my = sidx[i]; unsigned myk = skey[i];
        int r = 0;
        for (int j = 0; j < cnt; j++) {
            unsigned ok = skey[j]; int oj = sidx[j];
            r += (ok > myk) || (ok == myk && oj < my);
        }
        if (r == (int)rank - 1) { g_thr_key[e] = myk; g_tiecut[e] = my; }
    }
}

// ---------------- D: weighted accumulation (f32x2) ----------------
__global__ void __launch_bounds__(256) kD(const float* __restrict__ base) {
    __shared__ unsigned long long s_w[32][8];
    int tid = threadIdx.x;
    int we = tid >> 5, wr = tid & 31;
    unsigned long long accA[8], accB[8];
    #pragma unroll
    for (int e = 0; e < 8; e++) { accA[e] = 0ull; accB[e] = 0ull; }
    unsigned thr = g_thr_key[we];
    int cut = g_tiecut[we];
    const ulonglong2* b2 = (const ulonglong2*)base;
    for (int tile = blockIdx.x; tile < NB / 32; tile += gridDim.x) {
        int row0 = tile * 32;
        {
            int row = row0 + wr;
            float sim = g_sim[we * NB + row];
            unsigned key = tokey(sim);
            bool sel = (key > thr) || (key == thr && row <= cut);
            float w = sel ? (sqrtf(fmaxf(sim, 0.f)) * g_invnorm[row]) : 0.f;
            unsigned u = __float_as_uint(w);
            s_w[wr][we] = ((unsigned long long)u << 32) | u;
        }
        __syncthreads();
        #pragma unroll 2
        for (int r = 0; r < 32; r++) {
            ulonglong2 w01 = *(const ulonglong2*)&s_w[r][0];
            ulonglong2 w23 = *(const ulonglong2*)&s_w[r][2];
            ulonglong2 w45 = *(const ulonglong2*)&s_w[r][4];
            ulonglong2 w67 = *(const ulonglong2*)&s_w[r][6];
            unsigned long long any = w01.x | w01.y | w23.x | w23.y | w45.x | w45.y | w67.x | w67.y;
            if (any) {
                ulonglong2 v = b2[(size_t)(row0 + r) * 256 + tid];
                fma2(accA[0], w01.x, v.x); fma2(accB[0], w01.x, v.y);
                fma2(accA[1], w01.y, v.x); fma2(accB[1], w01.y, v.y);
                fma2(accA[2], w23.x, v.x); fma2(accB[2], w23.x, v.y);
                fma2(accA[3], w23.y, v.x); fma2(accB[3], w23.y, v.y);
                fma2(accA[4], w45.x, v.x); fma2(accB[4], w45.x, v.y);
                fma2(accA[5], w45.y, v.x); fma2(accB[5], w45.y, v.y);
                fma2(accA[6], w67.x, v.x); fma2(accB[6], w67.x, v.y);
                fma2(accA[7], w67.y, v.x); fma2(accB[7], w67.y, v.y);
            }
        }
        __syncthreads();
    }
    #pragma unroll
    for (int e = 0; e < 8; e++) {
        float ax, ay, az, aw;
        asm("mov.b64 {%0,%1}, %2;" : "=f"(ax), "=f"(ay) : "l"(accA[e]));
        asm("mov.b64 {%0,%1}, %2;" : "=f"(az), "=f"(aw) : "l"(accB[e]));
        atomicAdd(&g_approx[e][4 * tid + 0], ax);
        atomicAdd(&g_approx[e][4 * tid + 1], ay);
        atomicAdd(&g_approx[e][4 * tid + 2], az);
        atomicAdd(&g_approx[e][4 * tid + 3], aw);
    }
}

// ---------------- E: normalize approx ----------------
__global__ void __launch_bounds__(256) kE() {
    int e = blockIdx.x, tid = threadIdx.x;
    float4* a4 = (float4*)g_approx[e];
    float4 v = a4[tid];
    float ss = v.x * v.x + v.y * v.y + v.z * v.z + v.w * v.w;
    int lane = tid & 31, wid = tid >> 5;
    #pragma unroll
    for (int o = 16; o > 0; o >>= 1) ss += __shfl_xor_sync(0xFFFFFFFFu, ss, o);
    __shared__ float s_s[8];
    __shared__ float s_inv;
    if (lane == 0) s_s[wid] = ss;
    __syncthreads();
    if (tid == 0) {
        float t = 0.f;
        for (int i = 0; i < 8; i++) t += s_s[i];
        s_inv = rsqrtf(fmaxf(t, 1e-24f));
    }
    __syncthreads();
    float inv = s_inv;
    v.x *= inv; v.y *= inv; v.z *= inv; v.w *= inv;
    a4[tid] = v;
}

// ---------------- F: orthogonalize every feature row ----------------
__global__ void __launch_bounds__(256) kF(const float* __restrict__ feats, float* __restrict__ out) {
    int b = blockIdx.x;
    int e = b >> 7;
    int lane = threadIdx.x & 31, warp = threadIdx.x >> 5;
    int rowInEp = (b & 127) * 8 + warp;
    size_t off = ((size_t)e * DIM + rowInEp) * DIM;
    const float4* f4 = (const float4*)(feats + off);
    float4* o4 = (float4*)(out + off);
    const float4* a4 = (const float4*)g_approx[e];
    float4 v[8], a[8];
    float ss = 0.f, dd = 0.f;
    #pragma unroll
    for (int k = 0; k < 8; k++) {
        v[k] = f4[k * 32 + lane];
        a[k] = a4[k * 32 + lane];
        ss += v[k].x * v[k].x + v[k].y * v[k].y + v[k].z * v[k].z + v[k].w * v[k].w;
        dd += v[k].x * a[k].x + v[k].y * a[k].y + v[k].z * a[k].z + v[k].w * a[k].w;
    }
    #pragma unroll
    for (int o = 16; o > 0; o >>= 1) {
        ss += __shfl_xor_sync(0xFFFFFFFFu, ss, o);
        dd += __shfl_xor_sync(0xFFFFFFFFu, dd, o);
    }
    float invf = rsqrtf(fmaxf(ss, 1e-24f));
    float c = dd * invf;
    float sc = rsqrtf(fmaxf(1.0f - c * c, 1e-24f));
    #pragma unroll
    for (int k = 0; k < 8; k++) {
        float4 r;
        r.x = (v[k].x * invf - c * a[k].x) * sc;
        r.y = (v[k].y * invf - c * a[k].y) * sc;
        r.z = (v[k].z * invf - c * a[k].z) * sc;
        r.w = (v[k].w * invf - c * a[k].w) * sc;
        o4[k * 32 + lane] = r;
    }
}

// ---------------- launch ----------------
extern "C" void kernel_launch(void* const* d_in, const int* in_sizes, int n_in,
                              void* d_out, int out_size) {
    const float* feats = (const float*)d_in[0];
    const float* base  = (const float*)d_in[1];
    float* out = (float*)d_out;
    (void)in_sizes; (void)n_in; (void)out_size;

    kInit<<<296, 1024>>>();
    kA<<<NE, 1024>>>(feats);
    kB<<<1480, 128>>>(base);
    kHist2<<<dim3(49, NE), 1024>>>();
    kFind2<<<NE, 1024>>>();
    kCand<<<dim3(49, NE), 1024>>>();
    kResolve<<<NE, 256>>>();
    kD<<<592, 256>>>(base);
    kE<<<NE, 256>>>();
    kF<<<1024, 256>>>(feats, out);
}

// round 4
// speedup vs baseline: 1.3891x; 1.3066x over previous
#include <cuda_runtime.h>
#include <math.h>

#define NE    8
#define NB    100000
#define DIM   1024
#define NSUP  128
#define KSEL  15000u
#define MAXC  4096

// ---------------- scratch ----------------
__device__ float    g_q[NE][DIM];
__device__ float    g_sim[NE * NB];
__device__ float    g_invnorm[NB];
__device__ unsigned g_h1[NE][256];
__device__ unsigned g_h2[NE][65536];
__device__ unsigned g_prefix24[NE];
__device__ unsigned g_rank2[NE];
__device__ int      g_cand[NE][MAXC];
__device__ int      g_ccnt[NE];
__device__ unsigned g_thr_key[NE];
__device__ int      g_tiecut[NE];
__device__ float    g_approx[NE][DIM];

__device__ __forceinline__ unsigned tokey(float f) {
    unsigned b = __float_as_uint(f);
    return b ^ ((unsigned)((int)b >> 31) | 0x80000000u);
}

// ---------------- init ----------------
__global__ void kInit() {
    unsigned i = blockIdx.x * blockDim.x + threadIdx.x;
    unsigned stride = gridDim.x * blockDim.x;
    unsigned* h2 = &g_h2[0][0];
    for (unsigned k = i; k < NE * 65536u; k += stride) h2[k] = 0u;
    unsigned* h1 = &g_h1[0][0];
    for (unsigned k = i; k < NE * 256u; k += stride) h1[k] = 0u;
    float* ap = &g_approx[0][0];
    for (unsigned k = i; k < NE * DIM; k += stride) ap[k] = 0.0f;
    if (i < NE) g_ccnt[i] = 0;
}

// ---------------- A: per-episode support mean of normalized rows ----------------
__global__ void __launch_bounds__(1024) kA(const float* __restrict__ feats) {
    int e = blockIdx.x;
    int tid = threadIdx.x, lane = tid & 31, wid = tid >> 5;
    __shared__ float s_inv[NSUP];
    const float* fe = feats + (size_t)e * DIM * DIM;
    #pragma unroll
    for (int rr = 0; rr < NSUP / 32; rr++) {
        int r = wid + rr * 32;
        const float4* row4 = (const float4*)(fe + (size_t)r * DIM);
        float s = 0.f;
        #pragma unroll
        for (int k = 0; k < 8; k++) {
            float4 v = row4[k * 32 + lane];
            s += v.x * v.x + v.y * v.y + v.z * v.z + v.w * v.w;
        }
        #pragma unroll
        for (int o = 16; o > 0; o >>= 1) s += __shfl_xor_sync(0xFFFFFFFFu, s, o);
        if (lane == 0) s_inv[r] = rsqrtf(fmaxf(s, 1e-24f));
    }
    __syncthreads();
    float acc = 0.f;
    #pragma unroll 8
    for (int r = 0; r < NSUP; r++) acc += fe[(size_t)r * DIM + tid] * s_inv[r];
    g_q[e][tid] = acc;
}

// ---------------- B: sims (R1 float4 version, proven fast) ----------------
__global__ void __launch_bounds__(128) kB(const float* __restrict__ base) {
    __shared__ float4 sq[NE * 256];   // 32 KB
    for (int i = threadIdx.x; i < NE * 256; i += 128) sq[i] = ((const float4*)g_q)[i];
    __syncthreads();
    int lane = threadIdx.x & 31;
    int gw = (blockIdx.x * 128 + threadIdx.x) >> 5;
    int nw = (gridDim.x * 128) >> 5;
    for (int g = gw; g < NB / 4; g += nw) {
        const float4* p0 = (const float4*)(base + (size_t)(4 * g) * DIM);
        const float4* p1 = p0 + 256;
        const float4* p2 = p0 + 512;
        const float4* p3 = p0 + 768;
        float acc[4][8];
        float ss[4];
        #pragma unroll
        for (int r = 0; r < 4; r++) {
            ss[r] = 0.f;
            #pragma unroll
            for (int e = 0; e < 8; e++) acc[r][e] = 0.f;
        }
        #pragma unroll 2
        for (int k = 0; k < 8; k++) {
            float4 v0 = p0[k * 32 + lane];
            float4 v1 = p1[k * 32 + lane];
            float4 v2 = p2[k * 32 + lane];
            float4 v3 = p3[k * 32 + lane];
            ss[0] += v0.x * v0.x + v0.y * v0.y + v0.z * v0.z + v0.w * v0.w;
            ss[1] += v1.x * v1.x + v1.y * v1.y + v1.z * v1.z + v1.w * v1.w;
            ss[2] += v2.x * v2.x + v2.y * v2.y + v2.z * v2.z + v2.w * v2.w;
            ss[3] += v3.x * v3.x + v3.y * v3.y + v3.z * v3.z + v3.w * v3.w;
            #pragma unroll
            for (int e = 0; e < 8; e++) {
                float4 q = sq[e * 256 + k * 32 + lane];
                acc[0][e] += v0.x * q.x + v0.y * q.y + v0.z * q.z + v0.w * q.w;
                acc[1][e] += v1.x * q.x + v1.y * q.y + v1.z * q.z + v1.w * q.w;
                acc[2][e] += v2.x * q.x + v2.y * q.y + v2.z * q.z + v2.w * q.w;
                acc[3][e] += v3.x * q.x + v3.y * q.y + v3.z * q.z + v3.w * q.w;
            }
        }
        #pragma unroll
        for (int r = 0; r < 4; r++) {
            float s = ss[r];
            #pragma unroll
            for (int o = 16; o > 0; o >>= 1) s += __shfl_xor_sync(0xFFFFFFFFu, s, o);
            float inv = rsqrtf(fmaxf(s, 1e-24f));
            if (lane == 0) g_invnorm[4 * g + r] = inv;
            #pragma unroll
            for (int e = 0; e < 8; e++) {
                float d = acc[r][e];
                #pragma unroll
                for (int o = 16; o > 0; o >>= 1) d += __shfl_xor_sync(0xFFFFFFFFu, d, o);
                if (lane == 0) g_sim[e * NB + 4 * g + r] = d * inv;
            }
        }
    }
}

// ---------------- H1: 256-bin level-1 histogram, shared-privatized ----------------
__global__ void __launch_bounds__(1024) kH1() {
    int e = blockIdx.y;
    __shared__ unsigned h[256];
    int t = threadIdx.x;
    if (t < 256) h[t] = 0u;
    __syncthreads();
    const float* sims = g_sim + (size_t)e * NB;
    int i0 = blockIdx.x * 2048 + t;
    #pragma unroll
    for (int rr = 0; rr < 2; rr++) {
        int i = i0 + rr * 1024;
        if (i < NB) atomicAdd(&h[tokey(sims[i]) >> 24], 1u);
    }
    __syncthreads();
    if (t < 256) { unsigned c = h[t]; if (c) atomicAdd(&g_h1[e][t], c); }
}

// ---------------- selection helpers ----------------
__device__ __forceinline__ void find256(unsigned* h, unsigned* sfx, unsigned target,
                                        unsigned* obin, unsigned* orank) {
    int t = threadIdx.x;
    if (t < 256) sfx[t] = h[t];
    __syncthreads();
    #pragma unroll
    for (int o = 1; o < 256; o <<= 1) {
        unsigned v = 0;
        if (t < 256 && t + o < 256) v = sfx[t + o];
        __syncthreads();
        if (t < 256) sfx[t] += v;
        __syncthreads();
    }
    if (t < 256) {
        unsigned tot = sfx[t], above = tot - h[t];
        if (above < target && target <= tot) { *obin = (unsigned)t; if (orank) *orank = target - above; }
    }
    __syncthreads();
}

__device__ __forceinline__ void find64k(const unsigned* __restrict__ hist, unsigned target,
                                        unsigned* obin, unsigned* orank) {
    int t = threadIdx.x, lane = t & 31, wid = t >> 5;
    unsigned base = (unsigned)t * 64u;
    unsigned part = 0;
    #pragma unroll 8
    for (int j = 0; j < 64; j++) part += hist[base + j];
    unsigned x = part;
    #pragma unroll
    for (int o = 1; o < 32; o <<= 1) { unsigned y = __shfl_up_sync(0xFFFFFFFFu, x, o); if (lane >= o) x += y; }
    __shared__ unsigned s_ws[32];
    __shared__ unsigned s_total;
    if (lane == 31) s_ws[wid] = x;
    __syncthreads();
    if (wid == 0) {
        unsigned w = s_ws[lane];
        #pragma unroll
        for (int o = 1; o < 32; o <<= 1) { unsigned y = __shfl_up_sync(0xFFFFFFFFu, w, o); if (lane >= o) w += y; }
        s_ws[lane] = w;
        if (lane == 31) s_total = w;
    }
    __syncthreads();
    unsigned incl = x + (wid ? s_ws[wid - 1] : 0u);
    unsigned above = s_total - incl;
    if (above < target && target <= above + part) {
        unsigned cum = above;
        for (int j = 63; j >= 0; j--) {
            unsigned c = hist[base + j];
            if (cum + c >= target) { *obin = base + j; *orank = target - cum; break; }
            cum += c;
        }
    }
    __syncthreads();
}

// ---------------- Hist2: grid-wide filtered 16-bit histogram ----------------
__global__ void __launch_bounds__(1024) kHist2() {
    int e = blockIdx.y;
    int t = threadIdx.x;
    __shared__ unsigned h[256], sfx[256];
    __shared__ unsigned s_bin1;
    if (t < 256) h[t] = g_h1[e][t];
    __syncthreads();
    find256(h, sfx, KSEL, &s_bin1, 0);
    unsigned b1 = s_bin1;
    const float* sims = g_sim + (size_t)e * NB;
    int i0 = blockIdx.x * 2048 + t;
    #pragma unroll
    for (int rr = 0; rr < 2; rr++) {
        int i = i0 + rr * 1024;
        if (i < NB) {
            unsigned key = tokey(sims[i]);
            if ((key >> 24) == b1) atomicAdd(&g_h2[e][(key >> 8) & 0xFFFFu], 1u);
        }
    }
}

// ---------------- Find2: exact 24-bit prefix + rank ----------------
__global__ void __launch_bounds__(1024) kFind2() {
    int e = blockIdx.x;
    int t = threadIdx.x;
    __shared__ unsigned h[256], sfx[256];
    __shared__ unsigned s_bin1, s_rank1, s_bin2, s_rank2;
    if (t < 256) h[t] = g_h1[e][t];
    __syncthreads();
    find256(h, sfx, KSEL, &s_bin1, &s_rank1);
    find64k(g_h2[e], s_rank1, &s_bin2, &s_rank2);
    if (t == 0) {
        g_prefix24[e] = (s_bin1 << 16) | s_bin2;
        g_rank2[e] = s_rank2;
    }
}

// ---------------- Cand: grid-wide collect of 24-bit-prefix matches ----------------
__global__ void __launch_bounds__(1024) kCand() {
    int e = blockIdx.y;
    unsigned pfx = g_prefix24[e];
    const float* sims = g_sim + (size_t)e * NB;
    int i0 = blockIdx.x * 2048 + threadIdx.x;
    #pragma unroll
    for (int rr = 0; rr < 2; rr++) {
        int i = i0 + rr * 1024;
        if (i < NB) {
            unsigned key = tokey(sims[i]);
            if ((key >> 8) == pfx) {
                int p = atomicAdd(&g_ccnt[e], 1);
                if (p < MAXC) g_cand[e][p] = i;
            }
        }
    }
}

// ---------------- Resolve: exact 32-bit threshold + lowest-index tie cut ----------
__global__ void __launch_bounds__(256) kResolve() {
    int e = blockIdx.x;
    int cnt = min(g_ccnt[e], MAXC);
    unsigned rank = g_rank2[e];
    __shared__ int sidx[MAXC];
    __shared__ unsigned skey[MAXC];
    const float* sims = g_sim + (size_t)e * NB;
    for (int i = threadIdx.x; i < cnt; i += 256) {
        int idx = g_cand[e][i];
        sidx[i] = idx;
        skey[i] = tokey(sims[idx]);
    }
    __syncthreads();
    for (int i = threadIdx.x; i < cnt; i += 256) {
        int my = sidx[i]; unsigned myk = skey[i];
        int r = 0;
        for (int j = 0; j < cnt; j++) {
            unsigned ok = skey[j]; int oj = sidx[j];
            r += (ok > myk) || (ok == myk && oj < my);
        }
        if (r == (int)rank - 1) { g_thr_key[e] = myk; g_tiecut[e] = my; }
    }
}

// ---------------- D: weighted accumulation (R1 float4 version) ----------------
__global__ void __launch_bounds__(256) kD(const float* __restrict__ base) {
    __shared__ float s_w[32][8];
    int tid = threadIdx.x;
    int we = tid >> 5, wr = tid & 31;
    float4 acc[8];
    #pragma unroll
    for (int e = 0; e < 8; e++) acc[e] = make_float4(0.f, 0.f, 0.f, 0.f);
    unsigned thr = g_thr_key[we];
    int cut = g_tiecut[we];
    const float4* b4 = (const float4*)base;
    for (int tile = blockIdx.x; tile < NB / 32; tile += gridDim.x) {
        int row0 = tile * 32;
        {
            int row = row0 + wr;
            float sim = g_sim[we * NB + row];
            unsigned key = tokey(sim);
            bool sel = (key > thr) || (key == thr && row <= cut);
            s_w[wr][we] = sel ? (sqrtf(fmaxf(sim, 0.f)) * g_invnorm[row]) : 0.f;
        }
        __syncthreads();
        #pragma unroll 2
        for (int r = 0; r < 32; r++) {
            float4 wlo = *(const float4*)(&s_w[r][0]);
            float4 whi = *(const float4*)(&s_w[r][4]);
            unsigned any = __float_as_uint(wlo.x) | __float_as_uint(wlo.y) |
                           __float_as_uint(wlo.z) | __float_as_uint(wlo.w) |
                           __float_as_uint(whi.x) | __float_as_uint(whi.y) |
                           __float_as_uint(whi.z) | __float_as_uint(whi.w);
            if (any) {
                float4 v = b4[(size_t)(row0 + r) * 256 + tid];
                #define ACCUM(idx, wv) \
                    acc[idx].x += (wv) * v.x; acc[idx].y += (wv) * v.y; \
                    acc[idx].z += (wv) * v.z; acc[idx].w += (wv) * v.w;
                ACCUM(0, wlo.x) ACCUM(1, wlo.y) ACCUM(2, wlo.z) ACCUM(3, wlo.w)
                ACCUM(4, whi.x) ACCUM(5, whi.y) ACCUM(6, whi.z) ACCUM(7, whi.w)
                #undef ACCUM
            }
        }
        __syncthreads();
    }
    #pragma unroll
    for (int e = 0; e < 8; e++) {
        atomicAdd(&g_approx[e][4 * tid + 0], acc[e].x);
        atomicAdd(&g_approx[e][4 * tid + 1], acc[e].y);
        atomicAdd(&g_approx[e][4 * tid + 2], acc[e].z);
        atomicAdd(&g_approx[e][4 * tid + 3], acc[e].w);
    }
}

// ---------------- E: normalize approx ----------------
__global__ void __launch_bounds__(256) kE() {
    int e = blockIdx.x, tid = threadIdx.x;
    float4* a4 = (float4*)g_approx[e];
    float4 v = a4[tid];
    float ss = v.x * v.x + v.y * v.y + v.z * v.z + v.w * v.w;
    int lane = tid & 31, wid = tid >> 5;
    #pragma unroll
    for (int o = 16; o > 0; o >>= 1) ss += __shfl_xor_sync(0xFFFFFFFFu, ss, o);
    __shared__ float s_s[8];
    __shared__ float s_inv;
    if (lane == 0) s_s[wid] = ss;
    __syncthreads();
    if (tid == 0) {
        float t = 0.f;
        for (int i = 0; i < 8; i++) t += s_s[i];
        s_inv = rsqrtf(fmaxf(t, 1e-24f));
    }
    __syncthreads();
    float inv = s_inv;
    v.x *= inv; v.y *= inv; v.z *= inv; v.w *= inv;
    a4[tid] = v;
}

// ---------------- F: orthogonalize every feature row ----------------
__global__ void __launch_bounds__(256) kF(const float* __restrict__ feats, float* __restrict__ out) {
    int b = blockIdx.x;
    int e = b >> 7;
    int lane = threadIdx.x & 31, warp = threadIdx.x >> 5;
    int rowInEp = (b & 127) * 8 + warp;
    size_t off = ((size_t)e * DIM + rowInEp) * DIM;
    const float4* f4 = (const float4*)(feats + off);
    float4* o4 = (float4*)(out + off);
    const float4* a4 = (const float4*)g_approx[e];
    float4 v[8], a[8];
    float ss = 0.f, dd = 0.f;
    #pragma unroll
    for (int k = 0; k < 8; k++) {
        v[k] = f4[k * 32 + lane];
        a[k] = a4[k * 32 + lane];
        ss += v[k].x * v[k].x + v[k].y * v[k].y + v[k].z * v[k].z + v[k].w * v[k].w;
        dd += v[k].x * a[k].x + v[k].y * a[k].y + v[k].z * a[k].z + v[k].w * a[k].w;
    }
    #pragma unroll
    for (int o = 16; o > 0; o >>= 1) {
        ss += __shfl_xor_sync(0xFFFFFFFFu, ss, o);
        dd += __shfl_xor_sync(0xFFFFFFFFu, dd, o);
    }
    float invf = rsqrtf(fmaxf(ss, 1e-24f));
    float c = dd * invf;
    float sc = rsqrtf(fmaxf(1.0f - c * c, 1e-24f));
    #pragma unroll
    for (int k = 0; k < 8; k++) {
        float4 r;
        r.x = (v[k].x * invf - c * a[k].x) * sc;
        r.y = (v[k].y * invf - c * a[k].y) * sc;
        r.z = (v[k].z * invf - c * a[k].z) * sc;
        r.w = (v[k].w * invf - c * a[k].w) * sc;
        o4[k * 32 + lane] = r;
    }
}

// ---------------- launch ----------------
extern "C" void kernel_launch(void* const* d_in, const int* in_sizes, int n_in,
                              void* d_out, int out_size) {
    const float* feats = (const float*)d_in[0];
    const float* base  = (const float*)d_in[1];
    float* out = (float*)d_out;
    (void)in_sizes; (void)n_in; (void)out_size;

    kInit<<<296, 1024>>>();
    kA<<<NE, 1024>>>(feats);
    kB<<<1480, 128>>>(base);
    kH1<<<dim3(49, NE), 1024>>>();
    kHist2<<<dim3(49, NE), 1024>>>();
    kFind2<<<NE, 1024>>>();
    kCand<<<dim3(49, NE), 1024>>>();
    kResolve<<<NE, 256>>>();
    kD<<<592, 256>>>(base);
    kE<<<NE, 256>>>();
    kF<<<1024, 256>>>(feats, out);
}

// round 5
// speedup vs baseline: 1.5819x; 1.1388x over previous
#include <cuda_runtime.h>
#include <math.h>

#define NE    8
#define NB    100000
#define DIM   1024
#define NSUP  128
#define KSEL  15000u
#define MAXC  4096

// ---------------- scratch ----------------
__device__ float    g_q[NE][DIM];
__device__ float    g_sim[NE * NB];
__device__ float    g_invnorm[NB];
__device__ unsigned g_h1[NE][256];
__device__ unsigned g_h2[NE][65536];
__device__ unsigned g_prefix24[NE];
__device__ unsigned g_rank2[NE];
__device__ int      g_cand[NE][MAXC];
__device__ int      g_ccnt[NE];
__device__ unsigned g_thr_key[NE];
__device__ int      g_tiecut[NE];
__device__ float    g_approx[NE][DIM];

__device__ __forceinline__ unsigned tokey(float f) {
    unsigned b = __float_as_uint(f);
    return b ^ ((unsigned)((int)b >> 31) | 0x80000000u);
}

// ---------------- init ----------------
__global__ void kInit() {
    unsigned i = blockIdx.x * blockDim.x + threadIdx.x;
    unsigned stride = gridDim.x * blockDim.x;
    unsigned* h2 = &g_h2[0][0];
    for (unsigned k = i; k < NE * 65536u; k += stride) h2[k] = 0u;
    unsigned* h1 = &g_h1[0][0];
    for (unsigned k = i; k < NE * 256u; k += stride) h1[k] = 0u;
    float* ap = &g_approx[0][0];
    for (unsigned k = i; k < NE * DIM; k += stride) ap[k] = 0.0f;
    float* qq = &g_q[0][0];
    for (unsigned k = i; k < NE * DIM; k += stride) qq[k] = 0.0f;
    if (i < NE) g_ccnt[i] = 0;
}

// ---------------- A: support mean, 4 blocks per episode ----------------
__global__ void __launch_bounds__(1024) kA(const float* __restrict__ feats) {
    int e = blockIdx.x, chunk = blockIdx.y;
    int tid = threadIdx.x, lane = tid & 31, wid = tid >> 5;
    __shared__ float s_inv[32];
    const float* fe = feats + (size_t)e * DIM * DIM + (size_t)chunk * 32 * DIM;
    {   // warp wid: norm of local row wid
        const float4* row4 = (const float4*)(fe + (size_t)wid * DIM);
        float s = 0.f;
        #pragma unroll
        for (int k = 0; k < 8; k++) {
            float4 v = row4[k * 32 + lane];
            s += v.x * v.x + v.y * v.y + v.z * v.z + v.w * v.w;
        }
        #pragma unroll
        for (int o = 16; o > 0; o >>= 1) s += __shfl_xor_sync(0xFFFFFFFFu, s, o);
        if (lane == 0) s_inv[wid] = rsqrtf(fmaxf(s, 1e-24f));
    }
    __syncthreads();
    float acc = 0.f;
    #pragma unroll 8
    for (int r = 0; r < 32; r++) acc += fe[(size_t)r * DIM + tid] * s_inv[r];
    atomicAdd(&g_q[e][tid], acc);
}

// ---------------- B: sims (unchanged — proven fast) ----------------
__global__ void __launch_bounds__(128) kB(const float* __restrict__ base) {
    __shared__ float4 sq[NE * 256];   // 32 KB
    for (int i = threadIdx.x; i < NE * 256; i += 128) sq[i] = ((const float4*)g_q)[i];
    __syncthreads();
    int lane = threadIdx.x & 31;
    int gw = (blockIdx.x * 128 + threadIdx.x) >> 5;
    int nw = (gridDim.x * 128) >> 5;
    for (int g = gw; g < NB / 4; g += nw) {
        const float4* p0 = (const float4*)(base + (size_t)(4 * g) * DIM);
        const float4* p1 = p0 + 256;
        const float4* p2 = p0 + 512;
        const float4* p3 = p0 + 768;
        float acc[4][8];
        float ss[4];
        #pragma unroll
        for (int r = 0; r < 4; r++) {
            ss[r] = 0.f;
            #pragma unroll
            for (int e = 0; e < 8; e++) acc[r][e] = 0.f;
        }
        #pragma unroll 2
        for (int k = 0; k < 8; k++) {
            float4 v0 = p0[k * 32 + lane];
            float4 v1 = p1[k * 32 + lane];
            float4 v2 = p2[k * 32 + lane];
            float4 v3 = p3[k * 32 + lane];
            ss[0] += v0.x * v0.x + v0.y * v0.y + v0.z * v0.z + v0.w * v0.w;
            ss[1] += v1.x * v1.x + v1.y * v1.y + v1.z * v1.z + v1.w * v1.w;
            ss[2] += v2.x * v2.x + v2.y * v2.y + v2.z * v2.z + v2.w * v2.w;
            ss[3] += v3.x * v3.x + v3.y * v3.y + v3.z * v3.z + v3.w * v3.w;
            #pragma unroll
            for (int e = 0; e < 8; e++) {
                float4 q = sq[e * 256 + k * 32 + lane];
                acc[0][e] += v0.x * q.x + v0.y * q.y + v0.z * q.z + v0.w * q.w;
                acc[1][e] += v1.x * q.x + v1.y * q.y + v1.z * q.z + v1.w * q.w;
                acc[2][e] += v2.x * q.x + v2.y * q.y + v2.z * q.z + v2.w * q.w;
                acc[3][e] += v3.x * q.x + v3.y * q.y + v3.z * q.z + v3.w * q.w;
            }
        }
        #pragma unroll
        for (int r = 0; r < 4; r++) {
            float s = ss[r];
            #pragma unroll
            for (int o = 16; o > 0; o >>= 1) s += __shfl_xor_sync(0xFFFFFFFFu, s, o);
            float inv = rsqrtf(fmaxf(s, 1e-24f));
            if (lane == 0) g_invnorm[4 * g + r] = inv;
            #pragma unroll
            for (int e = 0; e < 8; e++) {
                float d = acc[r][e];
                #pragma unroll
                for (int o = 16; o > 0; o >>= 1) d += __shfl_xor_sync(0xFFFFFFFFu, d, o);
                if (lane == 0) g_sim[e * NB + 4 * g + r] = d * inv;
            }
        }
    }
}

// ---------------- H1: 256-bin level-1 histogram ----------------
__global__ void __launch_bounds__(1024) kH1() {
    int e = blockIdx.y;
    __shared__ unsigned h[256];
    int t = threadIdx.x;
    if (t < 256) h[t] = 0u;
    __syncthreads();
    const float* sims = g_sim + (size_t)e * NB;
    int i0 = blockIdx.x * 2048 + t;
    #pragma unroll
    for (int rr = 0; rr < 2; rr++) {
        int i = i0 + rr * 1024;
        if (i < NB) atomicAdd(&h[tokey(sims[i]) >> 24], 1u);
    }
    __syncthreads();
    if (t < 256) { unsigned c = h[t]; if (c) atomicAdd(&g_h1[e][t], c); }
}

// ---------------- selection helpers ----------------
__device__ __forceinline__ void find256(unsigned* h, unsigned* sfx, unsigned target,
                                        unsigned* obin, unsigned* orank) {
    int t = threadIdx.x;
    if (t < 256) sfx[t] = h[t];
    __syncthreads();
    #pragma unroll
    for (int o = 1; o < 256; o <<= 1) {
        unsigned v = 0;
        if (t < 256 && t + o < 256) v = sfx[t + o];
        __syncthreads();
        if (t < 256) sfx[t] += v;
        __syncthreads();
    }
    if (t < 256) {
        unsigned tot = sfx[t], above = tot - h[t];
        if (above < target && target <= tot) { *obin = (unsigned)t; if (orank) *orank = target - above; }
    }
    __syncthreads();
}

__device__ __forceinline__ void find64k(const unsigned* __restrict__ hist, unsigned target,
                                        unsigned* obin, unsigned* orank) {
    int t = threadIdx.x, lane = t & 31, wid = t >> 5;
    unsigned base = (unsigned)t * 64u;
    unsigned part = 0;
    #pragma unroll 8
    for (int j = 0; j < 64; j++) part += hist[base + j];
    unsigned x = part;
    #pragma unroll
    for (int o = 1; o < 32; o <<= 1) { unsigned y = __shfl_up_sync(0xFFFFFFFFu, x, o); if (lane >= o) x += y; }
    __shared__ unsigned s_ws[32];
    __shared__ unsigned s_total;
    if (lane == 31) s_ws[wid] = x;
    __syncthreads();
    if (wid == 0) {
        unsigned w = s_ws[lane];
        #pragma unroll
        for (int o = 1; o < 32; o <<= 1) { unsigned y = __shfl_up_sync(0xFFFFFFFFu, w, o); if (lane >= o) w += y; }
        s_ws[lane] = w;
        if (lane == 31) s_total = w;
    }
    __syncthreads();
    unsigned incl = x + (wid ? s_ws[wid - 1] : 0u);
    unsigned above = s_total - incl;
    if (above < target && target <= above + part) {
        unsigned cum = above;
        for (int j = 63; j >= 0; j--) {
            unsigned c = hist[base + j];
            if (cum + c >= target) { *obin = base + j; *orank = target - cum; break; }
            cum += c;
        }
    }
    __syncthreads();
}

// ---------------- Hist2: grid-wide filtered 16-bit histogram ----------------
__global__ void __launch_bounds__(1024) kHist2() {
    int e = blockIdx.y;
    int t = threadIdx.x;
    __shared__ unsigned h[256], sfx[256];
    __shared__ unsigned s_bin1;
    if (t < 256) h[t] = g_h1[e][t];
    __syncthreads();
    find256(h, sfx, KSEL, &s_bin1, 0);
    unsigned b1 = s_bin1;
    const float* sims = g_sim + (size_t)e * NB;
    int i0 = blockIdx.x * 2048 + t;
    #pragma unroll
    for (int rr = 0; rr < 2; rr++) {
        int i = i0 + rr * 1024;
        if (i < NB) {
            unsigned key = tokey(sims[i]);
            if ((key >> 24) == b1) atomicAdd(&g_h2[e][(key >> 8) & 0xFFFFu], 1u);
        }
    }
}

// ---------------- Find2: exact 24-bit prefix + rank ----------------
__global__ void __launch_bounds__(1024) kFind2() {
    int e = blockIdx.x;
    int t = threadIdx.x;
    __shared__ unsigned h[256], sfx[256];
    __shared__ unsigned s_bin1, s_rank1, s_bin2, s_rank2;
    if (t < 256) h[t] = g_h1[e][t];
    __syncthreads();
    find256(h, sfx, KSEL, &s_bin1, &s_rank1);
    find64k(g_h2[e], s_rank1, &s_bin2, &s_rank2);
    if (t == 0) {
        g_prefix24[e] = (s_bin1 << 16) | s_bin2;
        g_rank2[e] = s_rank2;
    }
}

// ---------------- Cand ----------------
__global__ void __launch_bounds__(1024) kCand() {
    int e = blockIdx.y;
    unsigned pfx = g_prefix24[e];
    const float* sims = g_sim + (size_t)e * NB;
    int i0 = blockIdx.x * 2048 + threadIdx.x;
    #pragma unroll
    for (int rr = 0; rr < 2; rr++) {
        int i = i0 + rr * 1024;
        if (i < NB) {
            unsigned key = tokey(sims[i]);
            if ((key >> 8) == pfx) {
                int p = atomicAdd(&g_ccnt[e], 1);
                if (p < MAXC) g_cand[e][p] = i;
            }
        }
    }
}

// ---------------- Resolve ----------------
__global__ void __launch_bounds__(256) kResolve() {
    int e = blockIdx.x;
    int cnt = min(g_ccnt[e], MAXC);
    unsigned rank = g_rank2[e];
    __shared__ int sidx[MAXC];
    __shared__ unsigned skey[MAXC];
    const float* sims = g_sim + (size_t)e * NB;
    for (int i = threadIdx.x; i < cnt; i += 256) {
        int idx = g_cand[e][i];
        sidx[i] = idx;
        skey[i] = tokey(sims[idx]);
    }
    __syncthreads();
    for (int i = threadIdx.x; i < cnt; i += 256) {
        int my = sidx[i]; unsigned myk = skey[i];
        int r = 0;
        for (int j = 0; j < cnt; j++) {
            unsigned ok = skey[j]; int oj = sidx[j];
            r += (ok > myk) || (ok == myk && oj < my);
        }
        if (r == (int)rank - 1) { g_thr_key[e] = myk; g_tiecut[e] = my; }
    }
}

// ---------------- D: warp-per-episode sparse weighted accumulation ----------------
__global__ void __launch_bounds__(256) kD(const float* __restrict__ base) {
    int e = threadIdx.x >> 5;         // warp = episode
    int lane = threadIdx.x & 31;
    unsigned thr = g_thr_key[e];
    int cut = g_tiecut[e];
    const float* sims = g_sim + (size_t)e * NB;
    const float4* b4 = (const float4*)base;
    float4 acc[8];
    #pragma unroll
    for (int i = 0; i < 8; i++) acc[i] = make_float4(0.f, 0.f, 0.f, 0.f);
    for (int tile = blockIdx.x; tile < NB / 16; tile += gridDim.x) {
        int row0 = tile * 16;
        float w = 0.f;
        if (lane < 16) {
            int row = row0 + lane;
            float sim = sims[row];
            unsigned key = tokey(sim);
            bool sel = (key > thr) || (key == thr && row <= cut);
            w = sel ? (sqrtf(fmaxf(sim, 0.f)) * g_invnorm[row]) : 0.f;
        }
        unsigned mask = __ballot_sync(0xFFFFFFFFu, w != 0.f);
        while (mask) {
            int r = __ffs(mask) - 1; mask &= mask - 1;
            float wr = __shfl_sync(0xFFFFFFFFu, w, r);
            const float4* rp = b4 + (size_t)(row0 + r) * 256;
            #pragma unroll
            for (int i = 0; i < 8; i++) {
                float4 v = rp[i * 32 + lane];
                acc[i].x += wr * v.x; acc[i].y += wr * v.y;
                acc[i].z += wr * v.z; acc[i].w += wr * v.w;
            }
        }
    }
    #pragma unroll
    for (int i = 0; i < 8; i++) {
        int c = (i * 32 + lane) * 4;
        atomicAdd(&g_approx[e][c + 0], acc[i].x);
        atomicAdd(&g_approx[e][c + 1], acc[i].y);
        atomicAdd(&g_approx[e][c + 2], acc[i].z);
        atomicAdd(&g_approx[e][c + 3], acc[i].w);
    }
}

// ---------------- E: normalize approx ----------------
__global__ void __launch_bounds__(256) kE() {
    int e = blockIdx.x, tid = threadIdx.x;
    float4* a4 = (float4*)g_approx[e];
    float4 v = a4[tid];
    float ss = v.x * v.x + v.y * v.y + v.z * v.z + v.w * v.w;
    int lane = tid & 31, wid = tid >> 5;
    #pragma unroll
    for (int o = 16; o > 0; o >>= 1) ss += __shfl_xor_sync(0xFFFFFFFFu, ss, o);
    __shared__ float s_s[8];
    __shared__ float s_inv;
    if (lane == 0) s_s[wid] = ss;
    __syncthreads();
    if (tid == 0) {
        float t = 0.f;
        for (int i = 0; i < 8; i++) t += s_s[i];
        s_inv = rsqrtf(fmaxf(t, 1e-24f));
    }
    __syncthreads();
    float inv = s_inv;
    v.x *= inv; v.y *= inv; v.z *= inv; v.w *= inv;
    a4[tid] = v;
}

// ---------------- F: orthogonalize every feature row ----------------
__global__ void __launch_bounds__(256) kF(const float* __restrict__ feats, float* __restrict__ out) {
    int b = blockIdx.x;
    int e = b >> 7;
    int lane = threadIdx.x & 31, warp = threadIdx.x >> 5;
    int rowInEp = (b & 127) * 8 + warp;
    size_t off = ((size_t)e * DIM + rowInEp) * DIM;
    const float4* f4 = (const float4*)(feats + off);
    float4* o4 = (float4*)(out + off);
    const float4* a4 = (const float4*)g_approx[e];
    float4 v[8], a[8];
    float ss = 0.f, dd = 0.f;
    #pragma unroll
    for (int k = 0; k < 8; k++) {
        v[k] = f4[k * 32 + lane];
        a[k] = a4[k * 32 + lane];
        ss += v[k].x * v[k].x + v[k].y * v[k].y + v[k].z * v[k].z + v[k].w * v[k].w;
        dd += v[k].x * a[k].x + v[k].y * a[k].y + v[k].z * a[k].z + v[k].w * a[k].w;
    }
    #pragma unroll
    for (int o = 16; o > 0; o >>= 1) {
        ss += __shfl_xor_sync(0xFFFFFFFFu, ss, o);
        dd += __shfl_xor_sync(0xFFFFFFFFu, dd, o);
    }
    float invf = rsqrtf(fmaxf(ss, 1e-24f));
    float c = dd * invf;
    float sc = rsqrtf(fmaxf(1.0f - c * c, 1e-24f));
    #pragma unroll
    for (int k = 0; k < 8; k++) {
        float4 r;
        r.x = (v[k].x * invf - c * a[k].x) * sc;
        r.y = (v[k].y * invf - c * a[k].y) * sc;
        r.z = (v[k].z * invf - c * a[k].z) * sc;
        r.w = (v[k].w * invf - c * a[k].w) * sc;
        o4[k * 32 + lane] = r;
    }
}

// ---------------- launch ----------------
extern "C" void kernel_launch(void* const* d_in, const int* in_sizes, int n_in,
                              void* d_out, int out_size) {
    const float* feats = (const float*)d_in[0];
    const float* base  = (const float*)d_in[1];
    float* out = (float*)d_out;
    (void)in_sizes; (void)n_in; (void)out_size;

    kInit<<<296, 1024>>>();
    kA<<<dim3(NE, 4), 1024>>>(feats);
    kB<<<1480, 128>>>(base);
    kH1<<<dim3(49, NE), 1024>>>();
    kHist2<<<dim3(49, NE), 1024>>>();
    kFind2<<<NE, 1024>>>();
    kCand<<<dim3(49, NE), 1024>>>();
    kResolve<<<NE, 256>>>();
    kD<<<296, 256>>>(base);
    kE<<<NE, 256>>>();
    kF<<<1024, 256>>>(feats, out);
}